// round 6
// baseline (speedup 1.0000x reference)
#include <cuda_runtime.h>
#include <math.h>
#include <stdint.h>

// Problem constants
#define C_DIM 64
#define D_DIM 32
#define H_DIM 96
#define W_DIM 96
#define B_DIM 2
#define WT 4          // w-tile per block
#define NTHREADS 512

// smem layout (floats), all offsets 16B-aligned
#define SV_OFF    0       // phase A/B: x tile [64][136]=8704 ; after mid-B sync: V [4 w(*2309)][c(*36)][e] (max 9227)
#define SQ_OFF    9240    // Q [4 w (*1185)][32 q (*36)][d] : 4740
#define SK_OFF    13980   // K : 4740
#define SAT_OFF   18720   // attn [4 w(*1152)][e(*36)][d] : 4608
#define SEX_OFF   23328   // softmax pair-exchange: 16 warps * 32 : 512
#define SBIAS_OFF 23840   // 128
#define SPOS_OFF  23968   // 1024
#define SMEM_FLOATS 24992
#define SMEM_BYTES (SMEM_FLOATS * 4)   // 99968 B -> 2 CTAs/SM
// sout staging overlays SQ..SK: sout[c*136 + w*32 + d], 64*136 = 8704 <= 9480

__device__ float g_tb[32];
__device__ float g_wpack[8192];   // prepacked tf32 W in A-fragment order

__device__ __forceinline__ float tf32r(float x) {
    uint32_t u;
    asm("cvt.rna.tf32.f32 %0, %1;" : "=r"(u) : "f"(x));
    return __uint_as_float(u);
}

__device__ __forceinline__ void mma_tf32(float* d, const float4& a, uint32_t b0, uint32_t b1) {
    const uint32_t* A = reinterpret_cast<const uint32_t*>(&a);
    asm volatile(
        "mma.sync.aligned.m16n8k8.row.col.f32.tf32.tf32.f32 "
        "{%0,%1,%2,%3}, {%4,%5,%6,%7}, {%8,%9}, {%0,%1,%2,%3};"
        : "+f"(d[0]), "+f"(d[1]), "+f"(d[2]), "+f"(d[3])
        : "r"(A[0]), "r"(A[1]), "r"(A[2]), "r"(A[3]), "r"(b0), "r"(b1));
}

__device__ __forceinline__ void cp16(float* smem_dst, const float* gmem_src) {
    unsigned s = (unsigned)__cvta_generic_to_shared(smem_dst);
    asm volatile("cp.async.ca.shared.global [%0], [%1], 16;" :: "r"(s), "l"(gmem_src));
}

// ---------------------------------------------------------------------------
// Setup kernel: text bias + weight prepack (fragment order, tf32-rounded)
// ---------------------------------------------------------------------------
__global__ void setup_kernel(const float* __restrict__ text_emb,
                             const float* __restrict__ wt,
                             const float* __restrict__ bt,
                             const float* __restrict__ wq,
                             const float* __restrict__ wk,
                             const float* __restrict__ wv) {
    __shared__ float mcol[256];
    int t = threadIdx.x;
    float s = 0.f;
    #pragma unroll
    for (int r = 0; r < 32; ++r) s += text_emb[r * 256 + t];
    mcol[t] = s * (1.0f / 32.0f);
    __syncthreads();
    int warp = t >> 5, lane = t & 31;
    for (int q = warp; q < 32; q += 8) {
        float acc = 0.f;
        #pragma unroll
        for (int k = 0; k < 8; ++k) acc += wt[q * 256 + lane + k * 32] * mcol[lane + k * 32];
        #pragma unroll
        for (int o = 16; o > 0; o >>= 1) acc += __shfl_xor_sync(0xffffffffu, acc, o);
        if (lane == 0) g_tb[q] = acc + bt[q];
    }
    // g_wpack[((mt*8+kt)*32 + lane)*4 + v] = W[mt*16+g+(v&1)*8][kt*8+tt+(v>>1)*4]
    #pragma unroll
    for (int it = 0; it < 32; ++it) {
        int idx  = t + it * 256;
        int v    = idx & 3;
        int ln   = (idx >> 2) & 31;
        int kt   = (idx >> 7) & 7;
        int mt   = idx >> 10;
        int g = ln >> 2, tt = ln & 3;
        int o = mt * 16 + g + (v & 1) * 8;
        int c = kt * 8 + tt + (v >> 1) * 4;
        float wval;
        if (o < 32)       wval = wq[o * 64 + c];
        else if (o < 64)  wval = wk[(o - 32) * 64 + c];
        else              wval = wv[(o - 64) * 64 + c];
        g_wpack[idx] = tf32r(wval);
    }
}

// ---------------------------------------------------------------------------
// Main fused kernel: one block per (b, h, w-tile of 4); 512 threads, 2 CTA/SM
// ---------------------------------------------------------------------------
__global__ __launch_bounds__(NTHREADS, 2)
void attn_kernel(const float* __restrict__ x,
                 const float* __restrict__ bq, const float* __restrict__ bk,
                 const float* __restrict__ bv,
                 const float* __restrict__ pos, const float* __restrict__ gamma,
                 float* __restrict__ out) {
    extern __shared__ float sm[];
    float* sxv   = sm + SV_OFF;    // x tile (A/B), V fragments afterwards
    float* sq    = sm + SQ_OFF;
    float* sk    = sm + SK_OFF;
    float* sat   = sm + SAT_OFF;
    float* sex   = sm + SEX_OFF;
    float* sbias = sm + SBIAS_OFF;
    float* spos  = sm + SPOS_OFF;
    float* sout  = sm + SQ_OFF;    // staging reuse (stride 136)

    const int tid = threadIdx.x;
    const int bid = blockIdx.x;
    const int nwT = W_DIM / WT;   // 24
    const int b   = bid / (H_DIM * nwT);
    const int rem = bid % (H_DIM * nwT);
    const int h   = rem / nwT;
    const int w0  = (rem % nwT) * WT;

    const int HW = H_DIM * W_DIM; // 9216
    const size_t base = (size_t)b * C_DIM * D_DIM * HW + (size_t)h * W_DIM + w0;

    // ---- Phase A: async x tile load (raw fp32; HMMA.TF32 truncates) ----
    #pragma unroll
    for (int it = 0; it < 4; ++it) {
        int i = tid + it * NTHREADS;          // 2048 float4s
        int c = i >> 5, d = i & 31;
        cp16(&sxv[c * 136 + d * 4], x + base + ((size_t)c * D_DIM + d) * HW);
    }
    if (tid < 128) {
        float bb;
        if (tid < 32)      bb = bq[tid] + g_tb[tid];
        else if (tid < 64) bb = bk[tid - 32] + g_tb[tid - 32];
        else               bb = bv[tid - 64];
        sbias[tid] = bb;
    }
    #pragma unroll
    for (int it = 0; it < 2; ++it) spos[tid + it * NTHREADS] = pos[tid + it * NTHREADS];
    asm volatile("cp.async.commit_group;");
    asm volatile("cp.async.wait_group 0;" ::: "memory");
    __syncthreads();

    // ---- Phase B: tf32 MMA GEMM  C[128 o][128 n] = W[128,64] * X[64,128] ----
    const int warp = tid >> 5, lane = tid & 31;
    const int g = lane >> 2, t = lane & 3;
    const int mw = warp & 7;        // o-group of 16: 0,1:Q 2,3:K 4..7:V
    const int nh = warp >> 3;       // n half (64 wide)

    {
        float acc[8][4];
        #pragma unroll
        for (int nt = 0; nt < 8; ++nt)
            #pragma unroll
            for (int v = 0; v < 4; ++v) acc[nt][v] = 0.f;

        const float4* wp4 = reinterpret_cast<const float4*>(g_wpack);
        #pragma unroll
        for (int kt = 0; kt < 8; ++kt) {
            float4 a = __ldg(&wp4[(mw * 8 + kt) * 32 + lane]);
            const float* xb0 = &sxv[(kt * 8 + t) * 136 + nh * 64 + g];
            const float* xb1 = &sxv[(kt * 8 + t + 4) * 136 + nh * 64 + g];
            #pragma unroll
            for (int nt = 0; nt < 8; ++nt) {
                uint32_t b0 = __float_as_uint(xb0[nt * 8]);
                uint32_t b1 = __float_as_uint(xb1[nt * 8]);
                mma_tf32(acc[nt], a, b0, b1);
            }
        }

        // Q/K epilogue (before mid-barrier): sq/sk[w*1185 + q*36 + d]
        if (mw < 4) {
            float* dst = (mw < 2) ? sq : sk;
            const int qb_ = (mw & 1) * 16;
            const int boff = (mw < 2) ? 0 : 32;
            const float qscale = (mw < 2) ? 0.17677669529663687f : 1.0f;
            #pragma unroll
            for (int nt = 0; nt < 8; ++nt) {
                #pragma unroll
                for (int v = 0; v < 4; ++v) {
                    int q = qb_ + g + (v >> 1) * 8;
                    int n = nh * 64 + nt * 8 + 2 * t + (v & 1);
                    int d = n >> 2, w = n & 3;
                    float val = acc[nt][v] + sbias[boff + q] + spos[q * 32 + d];
                    dst[w * 1185 + q * 36 + d] = tf32r(val * qscale);
                }
            }
        }
        __syncthreads();   // all X reads done; V may overwrite sxv

        // V epilogue: sv[w*2309 + c*36 + e]
        if (mw >= 4) {
            const int cbb = (mw - 4) * 16;
            #pragma unroll
            for (int nt = 0; nt < 8; ++nt) {
                #pragma unroll
                for (int v = 0; v < 4; ++v) {
                    int cch = cbb + g + (v >> 1) * 8;
                    int n = nh * 64 + nt * 8 + 2 * t + (v & 1);
                    int e = n >> 2, w = n & 3;
                    sxv[w * 2309 + cch * 36 + e] = tf32r(acc[nt][v] + sbias[64 + cch]);
                }
            }
        }
    }

    // ---- Phase C: scores via MMA + split softmax. warp = (w, dh, eh) ----
    const int aw = warp & 3;
    {
        const int dh = ((warp >> 2) & 1) * 16;
        const int eh = (warp >> 3) * 16;
        const float* qb = &sq[aw * 1185];   // [q*36 + d]
        const float* kb = &sk[aw * 1185];   // [q*36 + e]

        float fs[2][4];
        #pragma unroll
        for (int nt = 0; nt < 2; ++nt)
            #pragma unroll
            for (int v = 0; v < 4; ++v) fs[nt][v] = 0.f;

        #pragma unroll
        for (int kt = 0; kt < 4; ++kt) {
            float4 afr;   // A[m=d][k=q]
            afr.x = qb[(kt * 8 + t) * 36 + dh + g];
            afr.y = qb[(kt * 8 + t) * 36 + dh + g + 8];
            afr.z = qb[(kt * 8 + t + 4) * 36 + dh + g];
            afr.w = qb[(kt * 8 + t + 4) * 36 + dh + g + 8];
            #pragma unroll
            for (int nt = 0; nt < 2; ++nt) {   // B[k=q][n=e]
                uint32_t b0 = __float_as_uint(kb[(kt * 8 + t) * 36 + eh + nt * 8 + g]);
                uint32_t b1 = __float_as_uint(kb[(kt * 8 + t + 4) * 36 + eh + nt * 8 + g]);
                mma_tf32(fs[nt], afr, b0, b1);
            }
        }
        // fs[nt][v]: S[d = dh + g + (v>>1)*8][e = eh + nt*8 + 2t + (v&1)]

        // partial softmax over this warp's 16-e half
        float m0 = fmaxf(fmaxf(fs[0][0], fs[0][1]), fmaxf(fs[1][0], fs[1][1]));
        float m1 = fmaxf(fmaxf(fs[0][2], fs[0][3]), fmaxf(fs[1][2], fs[1][3]));
        m0 = fmaxf(m0, __shfl_xor_sync(0xffffffffu, m0, 1));
        m0 = fmaxf(m0, __shfl_xor_sync(0xffffffffu, m0, 2));
        m1 = fmaxf(m1, __shfl_xor_sync(0xffffffffu, m1, 1));
        m1 = fmaxf(m1, __shfl_xor_sync(0xffffffffu, m1, 2));

        float s0 = 0.f, s1 = 0.f;
        #pragma unroll
        for (int nt = 0; nt < 2; ++nt) {
            fs[nt][0] = __expf(fs[nt][0] - m0); s0 += fs[nt][0];
            fs[nt][1] = __expf(fs[nt][1] - m0); s0 += fs[nt][1];
            fs[nt][2] = __expf(fs[nt][2] - m1); s1 += fs[nt][2];
            fs[nt][3] = __expf(fs[nt][3] - m1); s1 += fs[nt][3];
        }
        s0 += __shfl_xor_sync(0xffffffffu, s0, 1);
        s0 += __shfl_xor_sync(0xffffffffu, s0, 2);
        s1 += __shfl_xor_sync(0xffffffffu, s1, 1);
        s1 += __shfl_xor_sync(0xffffffffu, s1, 2);

        // exchange with partner warp (other e-half): pair id = warp&7
        if (t == 0)
            *reinterpret_cast<float4*>(&sex[warp * 32 + g * 4]) = make_float4(m0, s0, m1, s1);
        const int barid = (warp & 7) + 1;
        asm volatile("bar.sync %0, %1;" :: "r"(barid), "r"(64) : "memory");
        float4 p = *reinterpret_cast<const float4*>(&sex[(warp ^ 8) * 32 + g * 4]);

        float mf0 = fmaxf(m0, p.x);
        float sf0 = s0 * __expf(m0 - mf0) + p.y * __expf(p.x - mf0);
        float r0  = __fdividef(__expf(m0 - mf0), sf0);
        float mf1 = fmaxf(m1, p.z);
        float sf1 = s1 * __expf(m1 - mf1) + p.w * __expf(p.z - mf1);
        float r1  = __fdividef(__expf(m1 - mf1), sf1);

        // transposed attn store: sat[w*1152 + e*36 + d]
        float* satw = &sat[aw * 1152];
        #pragma unroll
        for (int nt = 0; nt < 2; ++nt) {
            int e = eh + nt * 8 + 2 * t;
            satw[e * 36 + dh + g]           = tf32r(fs[nt][0] * r0);
            satw[(e + 1) * 36 + dh + g]     = tf32r(fs[nt][1] * r0);
            satw[e * 36 + dh + g + 8]       = tf32r(fs[nt][2] * r1);
            satw[(e + 1) * 36 + dh + g + 8] = tf32r(fs[nt][3] * r1);
        }
    }
    __syncthreads();   // V + attn complete; sq/sk dead -> sout

    // ---- Phase D: out[c][d] = V[c][e] @ attn[e][d]. warp = (w, ch, dq) ----
    {
        const int ch = ((warp >> 2) & 1) * 32;
        const int dq = (warp >> 3) * 16;
        const float* vb = &sxv[aw * 2309 + ch * 36];   // [c*36 + e]
        const float* ab = &sat[aw * 1152];             // [e*36 + d]

        float od[2][2][4];
        #pragma unroll
        for (int mt = 0; mt < 2; ++mt)
            #pragma unroll
            for (int nt = 0; nt < 2; ++nt)
                #pragma unroll
                for (int v = 0; v < 4; ++v) od[mt][nt][v] = 0.f;

        #pragma unroll
        for (int kt = 0; kt < 4; ++kt) {
            float4 av0, av1;   // A[m=c][k=e]
            av0.x = vb[g * 36 + kt * 8 + t];
            av0.y = vb[(g + 8) * 36 + kt * 8 + t];
            av0.z = vb[g * 36 + kt * 8 + t + 4];
            av0.w = vb[(g + 8) * 36 + kt * 8 + t + 4];
            av1.x = vb[(16 + g) * 36 + kt * 8 + t];
            av1.y = vb[(16 + g + 8) * 36 + kt * 8 + t];
            av1.z = vb[(16 + g) * 36 + kt * 8 + t + 4];
            av1.w = vb[(16 + g + 8) * 36 + kt * 8 + t + 4];
            #pragma unroll
            for (int nt = 0; nt < 2; ++nt) {   // B[k=e][n=d]
                uint32_t b0 = __float_as_uint(ab[(kt * 8 + t) * 36 + dq + nt * 8 + g]);
                uint32_t b1 = __float_as_uint(ab[(kt * 8 + t + 4) * 36 + dq + nt * 8 + g]);
                mma_tf32(od[0][nt], av0, b0, b1);
                mma_tf32(od[1][nt], av1, b0, b1);
            }
        }
        // od[mt][nt][v]: out[c = ch+mt*16+g+(v>>1)*8][d = dq + nt*8 + 2t + (v&1)]

        #pragma unroll
        for (int mt = 0; mt < 2; ++mt) {
            #pragma unroll
            for (int nt = 0; nt < 2; ++nt) {
                int c0 = ch + mt * 16 + g;
                int d0 = dq + nt * 8 + 2 * t;
                *reinterpret_cast<float2*>(&sout[c0 * 136 + aw * 32 + d0]) =
                    make_float2(od[mt][nt][0], od[mt][nt][1]);
                *reinterpret_cast<float2*>(&sout[(c0 + 8) * 136 + aw * 32 + d0]) =
                    make_float2(od[mt][nt][2], od[mt][nt][3]);
            }
        }
    }
    __syncthreads();

    // ---- Epilogue: out = g*attn_out + (1-g)*x, coalesced ----
    const float gm = gamma[0];
    const float g_ = 1.f / (1.f + __expf(-gm));
    const float g1 = 1.f - g_;
    #pragma unroll
    for (int it = 0; it < 4; ++it) {
        int i = tid + it * NTHREADS;
        int c = i >> 5, d = i & 31;
        size_t gaddr = base + ((size_t)c * D_DIM + d) * HW;
        float4 xv = *reinterpret_cast<const float4*>(x + gaddr);
        float4 r;
        r.x = g_ * sout[c * 136 +  0 + d] + g1 * xv.x;
        r.y = g_ * sout[c * 136 + 32 + d] + g1 * xv.y;
        r.z = g_ * sout[c * 136 + 64 + d] + g1 * xv.z;
        r.w = g_ * sout[c * 136 + 96 + d] + g1 * xv.w;
        *reinterpret_cast<float4*>(out + gaddr) = r;
    }
}

// ---------------------------------------------------------------------------
extern "C" void kernel_launch(void* const* d_in, const int* in_sizes, int n_in,
                              void* d_out, int out_size) {
    const float* x        = (const float*)d_in[0];
    const float* text_emb = (const float*)d_in[1];
    const float* wq       = (const float*)d_in[2];
    const float* bq       = (const float*)d_in[3];
    const float* wk       = (const float*)d_in[4];
    const float* bk       = (const float*)d_in[5];
    const float* wv       = (const float*)d_in[6];
    const float* bv       = (const float*)d_in[7];
    const float* wt       = (const float*)d_in[8];
    const float* bt       = (const float*)d_in[9];
    const float* pos      = (const float*)d_in[10];
    const float* gamma    = (const float*)d_in[11];
    float* out = (float*)d_out;

    cudaFuncSetAttribute(attn_kernel, cudaFuncAttributeMaxDynamicSharedMemorySize, SMEM_BYTES);

    setup_kernel<<<1, 256>>>(text_emb, wt, bt, wq, wk, wv);

    const int grid = B_DIM * H_DIM * (W_DIM / WT);  // 4608
    attn_kernel<<<grid, NTHREADS, SMEM_BYTES>>>(x, bq, bk, bv, pos, gamma, out);
}